// round 11
// baseline (speedup 1.0000x reference)
#include <cuda_runtime.h>
#include <math.h>

#define BSZ 2048
#define ND 128
#define HID 256
#define SHD 64
#define NSTEPS 8
#define MROWS 8
#define NBLOCKS (BSZ / MROWS)
#define NTHR 256

typedef unsigned long long ull;

// ---------- packed f32x2 helpers ----------
__device__ __forceinline__ void fma2(ull &c, ull a, ull b) {
    asm("fma.rn.f32x2 %0, %1, %2, %3;" : "=l"(c) : "l"(a), "l"(b), "l"(c));
}
__device__ __forceinline__ ull packdup(float x) {
    ull r; asm("mov.b64 %0, {%1, %2};" : "=l"(r) : "f"(x), "f"(x)); return r;
}
__device__ __forceinline__ void unpack2(ull v, float &x, float &y) {
    asm("mov.b64 {%0, %1}, %2;" : "=f"(x), "=f"(y) : "l"(v));
}

// ---------- transposed [len][8] shared rows (reads are row-broadcast) ----------
__device__ __forceinline__ void load_row8(const float* buf, int r, float v[8]) {
    const float4* p = reinterpret_cast<const float4*>(buf + r * 8);
    float4 c0 = p[0], c1 = p[1];
    v[0]=c0.x; v[1]=c0.y; v[2]=c0.z; v[3]=c0.w;
    v[4]=c1.x; v[5]=c1.y; v[6]=c1.z; v[7]=c1.w;
}
__device__ __forceinline__ void store_row8(float* buf, int r, const float v[8]) {
    float4* p = reinterpret_cast<float4*>(buf + r * 8);
    p[0] = make_float4(v[0], v[1], v[2], v[3]);
    p[1] = make_float4(v[4], v[5], v[6], v[7]);
}

// ---------- fast transcendentals (MUFU-based, absolute-accuracy safe) ----------
__device__ __forceinline__ float fast_tanh(float x) {
    float z = __expf(2.0f * x);
    return 1.0f - 2.0f / (z + 1.0f);
}
__device__ __forceinline__ float fast_softplus(float x) {
    float z = __expf(-fabsf(x));
    return fmaxf(x, 0.0f) + __logf(1.0f + z);
}
__device__ __forceinline__ float san(float x) { return isfinite(x) ? x : 0.f; }

// FMA one shared row (8 values) into accumulators, two weight columns
__device__ __forceinline__ void accum2(ull a0[4], ull a1[4], const float* in_buf,
                                       int k, ull w0, ull w1) {
    const ulonglong2* row = reinterpret_cast<const ulonglong2*>(in_buf + k * 8);
    ulonglong2 p0 = row[0], p1 = row[1];
    fma2(a0[0], p0.x, w0); fma2(a0[1], p0.y, w0);
    fma2(a0[2], p1.x, w0); fma2(a0[3], p1.y, w0);
    fma2(a1[0], p0.x, w1); fma2(a1[1], p0.y, w1);
    fma2(a1[2], p1.x, w1); fma2(a1[3], p1.y, w1);
}

// 2-column GEMM partial, adjacent cols (j2, j2+1), weights via float2, 4-deep prefetch.
// KS multiple of 4, >= 8. j2 even; j2+1 < N of the weight matrix.
__device__ __forceinline__ void gaccum2(float v0[8], float v1[8], const float* in_buf,
                                        const float* __restrict__ W, int ldw,
                                        int j2, int k0, int KS) {
    ull a0[4], a1[4];
    #pragma unroll
    for (int p = 0; p < 4; ++p) { a0[p] = 0ULL; a1[p] = 0ULL; }
    const int wld = ldw >> 1;
    const float2* __restrict__ wp = reinterpret_cast<const float2*>(W) + (size_t)k0 * wld + (j2 >> 1);
    float2 w[4];
    #pragma unroll
    for (int u = 0; u < 4; ++u) w[u] = wp[(size_t)u * wld];
    wp += (size_t)4 * wld;
    for (int kk = 0; kk < KS - 4; kk += 4) {
        float2 wn[4];
        #pragma unroll
        for (int u = 0; u < 4; ++u) wn[u] = wp[(size_t)u * wld];
        wp += (size_t)4 * wld;
        #pragma unroll
        for (int u = 0; u < 4; ++u)
            accum2(a0, a1, in_buf, k0 + kk + u, packdup(w[u].x), packdup(w[u].y));
        #pragma unroll
        for (int u = 0; u < 4; ++u) w[u] = wn[u];
    }
    #pragma unroll
    for (int u = 0; u < 4; ++u)
        accum2(a0, a1, in_buf, k0 + KS - 4 + u, packdup(w[u].x), packdup(w[u].y));
    #pragma unroll
    for (int p = 0; p < 4; ++p) { unpack2(a0[p], v0[2*p], v0[2*p+1]); unpack2(a1[p], v1[2*p], v1[2*p+1]); }
}

// warp-level reduce of 8 per-row partials; lane 0 holds sums
__device__ __forceinline__ void warp_reduce8(float sq[8]) {
    #pragma unroll
    for (int off = 16; off > 0; off >>= 1) {
        #pragma unroll
        for (int m = 0; m < 8; ++m)
            sq[m] += __shfl_down_sync(0xffffffffu, sq[m], off);
    }
}

__global__ void __launch_bounds__(NTHR, 3)
node_kernel(const float* __restrict__ y0, const float* __restrict__ tv,
            const float* __restrict__ noise,
            const float* __restrict__ fw1, const float* __restrict__ fb1,
            const float* __restrict__ fw2, const float* __restrict__ fb2,
            const float* __restrict__ fw3, const float* __restrict__ fb3,
            const float* __restrict__ amw1, const float* __restrict__ amb1,
            const float* __restrict__ amw2, const float* __restrict__ amb2,
            const float* __restrict__ amw3, const float* __restrict__ amb3,
            const float* __restrict__ alw1, const float* __restrict__ alb1,
            const float* __restrict__ alw2, const float* __restrict__ alb2,
            const float* __restrict__ alw3, const float* __restrict__ alb3,
            const float* __restrict__ kw, float* __restrict__ out)
{
    extern __shared__ float smem[];
    float* xs   = smem;              // 1024  [128][8]
    float* h1   = xs + 1024;         // 2048  [256][8]
    float* h2   = h1 + 2048;         // 2048
    float* fo   = h2 + 2048;         // 1024
    float* ko   = fo + 1024;         // 1024
    float* mo   = ko + 1024;         // 1024
    float* lso  = mo + 1024;         // 1024
    float* go   = lso + 1024;        // 1024  (f+g)
    float* ubf  = go + 1024;         // 1024
    float* ubg  = ubf + 1024;        // 1024
    float* a1m  = ubg + 1024;        // 512   [64][8]
    float* a1l  = a1m + 512;         // 512
    float* a2m  = a1l + 512;         // 512
    float* a2l  = a2m + 512;         // 512
    float* cb   = a2l + 512;         // 4096  partial scratch [512][8]
    float* redk = cb + 4096;         // 16
    float* redf = redk + 16;         // 32
    float* redg = redf + 32;         // 32
    float* kn2s = redg + 32;         // 8

    const int tid = threadIdx.x;
    const int r0 = blockIdx.x * MROWS;
    const float dt = tv[1] - tv[0];
    const int ewj = tid & 127;       // elementwise: col j
    const int ewc = tid >> 7;        // elementwise: chunk c (0/1), rows 4c..4c+3

    // load y0 tile (transposed [128][8]); emit output step 0
    {
        float a[4];
        #pragma unroll
        for (int q = 0; q < 4; ++q) {
            int m = 4 * ewc + q;
            float val = y0[(size_t)(r0 + m) * ND + ewj];
            out[(size_t)(r0 + m) * ND + ewj] = val;
            a[q] = val;
        }
        reinterpret_cast<float4*>(xs + ewj * 8)[ewc] = make_float4(a[0], a[1], a[2], a[3]);
    }
    __syncthreads();

    for (int step = 0; step < NSTEPS; ++step) {
        float v0[8], v1[8];
        // noise prefetch (consumed in stage E)
        float nse[4];
        {
            const float* np = noise + (size_t)step * BSZ * ND + (size_t)(r0 + 4 * ewc) * ND + ewj;
            #pragma unroll
            for (int q = 0; q < 4; ++q) nse[q] = np[(size_t)q * ND];
        }

        // ======== Stage A: f1(128thr,2col) || k(64thr,2col) || am1(32thr,2col) || al1(32thr,2col) ========
        if (tid < 128) {
            int j2 = 2 * tid;
            gaccum2(v0, v1, xs, fw1, HID, j2, 0, ND);
            float2 b = reinterpret_cast<const float2*>(fb1)[tid];
            #pragma unroll
            for (int m = 0; m < 8; ++m) { v0[m] = fast_tanh(v0[m] + b.x); v1[m] = fast_tanh(v1[m] + b.y); }
            store_row8(h1, j2, v0); store_row8(h1, j2 + 1, v1);
        } else if (tid < 192) {
            int t = tid - 128, j2 = 2 * t;
            gaccum2(v0, v1, xs, kw, ND, j2, 0, ND);
            float sq[8];
            #pragma unroll
            for (int m = 0; m < 8; ++m) {
                v0[m] = fast_tanh(v0[m]); v1[m] = fast_tanh(v1[m]);
                sq[m] = v0[m] * v0[m] + v1[m] * v1[m];
            }
            store_row8(ko, j2, v0); store_row8(ko, j2 + 1, v1);
            warp_reduce8(sq);
            if ((tid & 31) == 0) {
                int w = (tid - 128) >> 5;
                #pragma unroll
                for (int m = 0; m < 8; ++m) redk[w * 8 + m] = sq[m];
            }
        } else if (tid < 224) {
            int t = tid - 192, j2 = 2 * t;
            gaccum2(v0, v1, xs, amw1, SHD, j2, 0, ND);
            float2 b = reinterpret_cast<const float2*>(amb1)[t];
            #pragma unroll
            for (int m = 0; m < 8; ++m) { v0[m] = fmaxf(v0[m] + b.x, 0.f); v1[m] = fmaxf(v1[m] + b.y, 0.f); }
            store_row8(a1m, j2, v0); store_row8(a1m, j2 + 1, v1);
        } else {
            int t = tid - 224, j2 = 2 * t;
            gaccum2(v0, v1, xs, alw1, SHD, j2, 0, ND);
            float2 b = reinterpret_cast<const float2*>(alb1)[t];
            #pragma unroll
            for (int m = 0; m < 8; ++m) { v0[m] = fmaxf(v0[m] + b.x, 0.f); v1[m] = fmaxf(v1[m] + b.y, 0.f); }
            store_row8(a1l, j2, v0); store_row8(a1l, j2 + 1, v1);
        }
        __syncthreads();

        // ======== Stage B: f2 (2 cols/thread, K split over 2 halves) ========
        {
            int t = tid & 127, s = tid >> 7, j2 = 2 * t;
            gaccum2(v0, v1, h1, fw2, HID, j2, s * 128, 128);
            if (s == 1) { store_row8(cb, j2, v0); store_row8(cb, j2 + 1, v1); }
        }
        __syncthreads();

        // ======== Stage B2: h2 combine (128thr) || am2 (32thr,2col) || al2 (32thr,2col) ========
        if (tid < 128) {
            int j2 = 2 * tid;
            float w0[8], w1[8];
            load_row8(cb, j2, w0); load_row8(cb, j2 + 1, w1);
            float2 b = reinterpret_cast<const float2*>(fb2)[tid];
            #pragma unroll
            for (int m = 0; m < 8; ++m) {
                v0[m] = fast_softplus(v0[m] + w0[m] + b.x);
                v1[m] = fast_softplus(v1[m] + w1[m] + b.y);
            }
            store_row8(h2, j2, v0); store_row8(h2, j2 + 1, v1);
            if (tid < 8) kn2s[tid] = redk[tid] + redk[8 + tid];
        } else if (tid < 160) {
            int t = tid - 128, j2 = 2 * t;     // am2: 64 cols over 32 thr
            gaccum2(v0, v1, a1m, amw2, SHD, j2, 0, SHD);
            float2 b = reinterpret_cast<const float2*>(amb2)[t];
            #pragma unroll
            for (int m = 0; m < 8; ++m) { v0[m] = fmaxf(v0[m] + b.x, 0.f); v1[m] = fmaxf(v1[m] + b.y, 0.f); }
            store_row8(a2m, j2, v0); store_row8(a2m, j2 + 1, v1);
        } else if (tid < 192) {
            int t = tid - 160, j2 = 2 * t;     // al2
            gaccum2(v0, v1, a1l, alw2, SHD, j2, 0, SHD);
            float2 b = reinterpret_cast<const float2*>(alb2)[t];
            #pragma unroll
            for (int m = 0; m < 8; ++m) { v0[m] = fmaxf(v0[m] + b.x, 0.f); v1[m] = fmaxf(v1[m] + b.y, 0.f); }
            store_row8(a2l, j2, v0); store_row8(a2l, j2 + 1, v1);
        }
        __syncthreads();

        // ======== Stage C1: f3 — 2-col x 4 K-splits over all 256 thr; ALL slices to cb ========
        {
            int cg = tid >> 2, s = tid & 3, j2 = 2 * cg;
            gaccum2(v0, v1, h2, fw3, ND, j2, s * 64, 64);
            store_row8(cb, s * 128 + j2, v0);
            store_row8(cb, s * 128 + j2 + 1, v1);
        }
        __syncthreads();

        // ======== Stage C2: f3 combine (64thr,2col) || am3 (64thr,2col) || al3 (64thr,2col) ========
        if (tid < 64) {
            int j2 = 2 * tid;
            float acc0[8], acc1[8], t8[8];
            load_row8(cb, j2, acc0); load_row8(cb, j2 + 1, acc1);
            #pragma unroll
            for (int s = 1; s < 4; ++s) {
                load_row8(cb, s * 128 + j2, t8);
                #pragma unroll
                for (int m = 0; m < 8; ++m) acc0[m] += t8[m];
                load_row8(cb, s * 128 + j2 + 1, t8);
                #pragma unroll
                for (int m = 0; m < 8; ++m) acc1[m] += t8[m];
            }
            float2 b = reinterpret_cast<const float2*>(fb3)[tid];
            #pragma unroll
            for (int m = 0; m < 8; ++m) { acc0[m] += b.x; acc1[m] += b.y; }
            store_row8(fo, j2, acc0); store_row8(fo, j2 + 1, acc1);
        } else if (tid < 128) {
            int t = tid - 64, j2 = 2 * t;      // am3: 128 cols over 64 thr
            gaccum2(v0, v1, a2m, amw3, ND, j2, 0, SHD);
            float2 b = reinterpret_cast<const float2*>(amb3)[t];
            #pragma unroll
            for (int m = 0; m < 8; ++m) { v0[m] = fast_tanh(v0[m] + b.x); v1[m] = fast_tanh(v1[m] + b.y); }
            store_row8(mo, j2, v0); store_row8(mo, j2 + 1, v1);
        } else if (tid < 192) {
            int t = tid - 128, j2 = 2 * t;     // al3
            gaccum2(v0, v1, a2l, alw3, ND, j2, 0, SHD);
            float2 b = reinterpret_cast<const float2*>(alb3)[t];
            #pragma unroll
            for (int m = 0; m < 8; ++m) { v0[m] += b.x; v1[m] += b.y; }
            store_row8(lso, j2, v0); store_row8(lso, j2 + 1, v1);
        }
        __syncthreads();

        // ======== Stage E: g, f+g, u_f, u_g (elementwise float4) ========
        {
            float4 kv = reinterpret_cast<const float4*>(ko + ewj * 8)[ewc];
            float4 fv = reinterpret_cast<const float4*>(fo + ewj * 8)[ewc];
            float4 mv = reinterpret_cast<const float4*>(mo + ewj * 8)[ewc];
            float4 lv = reinterpret_cast<const float4*>(lso + ewj * 8)[ewc];
            float kk[4] = {kv.x, kv.y, kv.z, kv.w};
            float ff[4] = {fv.x, fv.y, fv.z, fv.w};
            float mm[4] = {mv.x, mv.y, mv.z, mv.w};
            float ll[4] = {lv.x, lv.y, lv.z, lv.w};
            float gs[4], uf[4], ug[4];
            #pragma unroll
            for (int q = 0; q < 4; ++q) {
                float sd = fast_softplus(san(ll[q]));
                float g = fast_tanh(san(mm[q]) + sd * nse[q]);
                float om = 1.f - kk[q] * kk[q];
                gs[q] = ff[q] + g;
                uf[q] = om * ff[q];
                ug[q] = om * g;
            }
            reinterpret_cast<float4*>(go + ewj * 8)[ewc] = make_float4(gs[0], gs[1], gs[2], gs[3]);
            reinterpret_cast<float4*>(ubf + ewj * 8)[ewc] = make_float4(uf[0], uf[1], uf[2], uf[3]);
            reinterpret_cast<float4*>(ubg + ewj * 8)[ewc] = make_float4(ug[0], ug[1], ug[2], ug[3]);
        }
        __syncthreads();

        // ======== Stage F: jacf (128thr, 2col x 2ks) || jacg (128thr, 2col x 2ks) ========
        if (tid < 128) {
            int cg = tid >> 1, s = tid & 1, j2 = 2 * cg;
            gaccum2(v0, v1, ubf, kw, ND, j2, s * 64, 64);
            store_row8(cb, s * 256 + j2, v0); store_row8(cb, s * 256 + j2 + 1, v1);
        } else {
            int t = tid - 128, cg = t >> 1, s = t & 1, j2 = 2 * cg;
            gaccum2(v0, v1, ubg, kw, ND, j2, s * 64, 64);
            store_row8(cb, s * 256 + 128 + j2, v0); store_row8(cb, s * 256 + 128 + j2 + 1, v1);
        }
        __syncthreads();

        // ======== Stage F2: combine + reduce ========
        if (tid < 128) {
            float va[8], wa[8];
            load_row8(cb, tid, va); load_row8(cb, 256 + tid, wa);
            float sq[8];
            #pragma unroll
            for (int m = 0; m < 8; ++m) { float x = va[m] + wa[m]; sq[m] = x * x; }
            warp_reduce8(sq);
            if ((tid & 31) == 0) {
                int w = tid >> 5;
                #pragma unroll
                for (int m = 0; m < 8; ++m) redf[w * 8 + m] = sq[m];
            }
        } else {
            int col = tid - 128;
            float va[8], wa[8], kr[8];
            load_row8(cb, 128 + col, va); load_row8(cb, 384 + col, wa);
            load_row8(ko, col, kr);
            float sq[8];
            #pragma unroll
            for (int m = 0; m < 8; ++m) sq[m] = (va[m] + wa[m]) * kr[m];
            warp_reduce8(sq);
            if ((tid & 31) == 0) {
                int w = (tid - 128) >> 5;
                #pragma unroll
                for (int m = 0; m < 8; ++m) redg[w * 8 + m] = sq[m];
            }
        }
        __syncthreads();

        // ======== Update: inline mask + Euler + output ========
        {
            float sclq[4];
            #pragma unroll
            for (int q = 0; q < 4; ++q) {
                int m = 4 * ewc + q;
                float kn2 = kn2s[m];
                float jf2 = redf[m] + redf[8 + m] + redf[16 + m] + redf[24 + m];
                float c2v = redg[m] + redg[8 + m] + redg[16 + m] + redg[24 + m];
                float kn = sqrtf(kn2);
                float kn9 = kn2 * kn2 * kn2 * kn2 * kn;
                float c1 = sqrtf(jf2) - 60.0f * kn9;
                float c2 = c2v - 20.0f * kn9 * kn;
                bool mask = (c1 > 1e-8f) || (c2 < -1e-8f);
                sclq[q] = mask ? (0.5f * dt) : dt;
            }
            float4 xv = reinterpret_cast<const float4*>(xs + ewj * 8)[ewc];
            float4 dv = reinterpret_cast<const float4*>(go + ewj * 8)[ewc];
            float x[4] = {xv.x, xv.y, xv.z, xv.w};
            float d[4] = {dv.x, dv.y, dv.z, dv.w};
            float o[4];
            float* ob = out + (size_t)(step + 1) * BSZ * ND;
            #pragma unroll
            for (int q = 0; q < 4; ++q) {
                int m = 4 * ewc + q;
                o[q] = x[q] + d[q] * sclq[q];
                ob[(size_t)(r0 + m) * ND + ewj] = o[q];
            }
            reinterpret_cast<float4*>(xs + ewj * 8)[ewc] = make_float4(o[0], o[1], o[2], o[3]);
        }
        __syncthreads();
    }
}

extern "C" void kernel_launch(void* const* d_in, const int* in_sizes, int n_in,
                              void* d_out, int out_size) {
    (void)in_sizes; (void)n_in; (void)out_size;
    const float* y0   = (const float*)d_in[0];
    const float* tv   = (const float*)d_in[1];
    const float* nz   = (const float*)d_in[2];
    const float* fw1  = (const float*)d_in[3];
    const float* fb1  = (const float*)d_in[4];
    const float* fw2  = (const float*)d_in[5];
    const float* fb2  = (const float*)d_in[6];
    const float* fw3  = (const float*)d_in[7];
    const float* fb3  = (const float*)d_in[8];
    const float* amw1 = (const float*)d_in[9];
    const float* amb1 = (const float*)d_in[10];
    const float* amw2 = (const float*)d_in[11];
    const float* amb2 = (const float*)d_in[12];
    const float* amw3 = (const float*)d_in[13];
    const float* amb3 = (const float*)d_in[14];
    const float* alw1 = (const float*)d_in[15];
    const float* alb1 = (const float*)d_in[16];
    const float* alw2 = (const float*)d_in[17];
    const float* alb2 = (const float*)d_in[18];
    const float* alw3 = (const float*)d_in[19];
    const float* alb3 = (const float*)d_in[20];
    const float* kw   = (const float*)d_in[21];
    float* out = (float*)d_out;

    const int shmem = 18520 * sizeof(float);  // ~74.1 KB -> 2 blocks/SM
    cudaFuncSetAttribute(node_kernel, cudaFuncAttributeMaxDynamicSharedMemorySize, shmem);
    node_kernel<<<NBLOCKS, NTHR, shmem>>>(
        y0, tv, nz, fw1, fb1, fw2, fb2, fw3, fb3,
        amw1, amb1, amw2, amb2, amw3, amb3,
        alw1, alb1, alw2, alb2, alw3, alb3, kw, out);
}

// round 12
// speedup vs baseline: 1.0279x; 1.0279x over previous
#include <cuda_runtime.h>
#include <math.h>

#define BSZ 2048
#define ND 128
#define HID 256
#define SHD 64
#define NSTEPS 8
#define MROWS 8
#define NBLOCKS (BSZ / MROWS)
#define NTHR 256

typedef unsigned long long ull;

// ---------- packed f32x2 helpers ----------
__device__ __forceinline__ void fma2(ull &c, ull a, ull b) {
    asm("fma.rn.f32x2 %0, %1, %2, %3;" : "=l"(c) : "l"(a), "l"(b), "l"(c));
}
__device__ __forceinline__ ull packdup(float x) {
    ull r; asm("mov.b64 %0, {%1, %2};" : "=l"(r) : "f"(x), "f"(x)); return r;
}
__device__ __forceinline__ void unpack2(ull v, float &x, float &y) {
    asm("mov.b64 {%0, %1}, %2;" : "=f"(x), "=f"(y) : "l"(v));
}

// ---------- transposed [len][8] shared rows (reads are row-broadcast) ----------
__device__ __forceinline__ void load_row8(const float* buf, int r, float v[8]) {
    const float4* p = reinterpret_cast<const float4*>(buf + r * 8);
    float4 c0 = p[0], c1 = p[1];
    v[0]=c0.x; v[1]=c0.y; v[2]=c0.z; v[3]=c0.w;
    v[4]=c1.x; v[5]=c1.y; v[6]=c1.z; v[7]=c1.w;
}
__device__ __forceinline__ void store_row8(float* buf, int r, const float v[8]) {
    float4* p = reinterpret_cast<float4*>(buf + r * 8);
    p[0] = make_float4(v[0], v[1], v[2], v[3]);
    p[1] = make_float4(v[4], v[5], v[6], v[7]);
}

// ---------- fast transcendentals (MUFU-based, absolute-accuracy safe) ----------
__device__ __forceinline__ float fast_tanh(float x) {
    float z = __expf(2.0f * x);
    return 1.0f - 2.0f / (z + 1.0f);
}
__device__ __forceinline__ float fast_softplus(float x) {
    float z = __expf(-fabsf(x));
    return fmaxf(x, 0.0f) + __logf(1.0f + z);
}
__device__ __forceinline__ float san(float x) { return isfinite(x) ? x : 0.f; }

// FMA one shared row (8 values) into accumulators, two weight columns
__device__ __forceinline__ void accum2(ull a0[4], ull a1[4], const float* in_buf,
                                       int k, ull w0, ull w1) {
    const ulonglong2* row = reinterpret_cast<const ulonglong2*>(in_buf + k * 8);
    ulonglong2 p0 = row[0], p1 = row[1];
    fma2(a0[0], p0.x, w0); fma2(a0[1], p0.y, w0);
    fma2(a0[2], p1.x, w0); fma2(a0[3], p1.y, w0);
    fma2(a1[0], p0.x, w1); fma2(a1[1], p0.y, w1);
    fma2(a1[2], p1.x, w1); fma2(a1[3], p1.y, w1);
}

// 2-column GEMM partial, adjacent cols (j2, j2+1), weights via float2, 4-deep prefetch.
// KS multiple of 4, >= 8. j2 even; j2+1 < N of the weight matrix.
__device__ __forceinline__ void gaccum2(float v0[8], float v1[8], const float* in_buf,
                                        const float* __restrict__ W, int ldw,
                                        int j2, int k0, int KS) {
    ull a0[4], a1[4];
    #pragma unroll
    for (int p = 0; p < 4; ++p) { a0[p] = 0ULL; a1[p] = 0ULL; }
    const int wld = ldw >> 1;
    const float2* __restrict__ wp = reinterpret_cast<const float2*>(W) + (size_t)k0 * wld + (j2 >> 1);
    float2 w[4];
    #pragma unroll
    for (int u = 0; u < 4; ++u) w[u] = wp[(size_t)u * wld];
    wp += (size_t)4 * wld;
    for (int kk = 0; kk < KS - 4; kk += 4) {
        float2 wn[4];
        #pragma unroll
        for (int u = 0; u < 4; ++u) wn[u] = wp[(size_t)u * wld];
        wp += (size_t)4 * wld;
        #pragma unroll
        for (int u = 0; u < 4; ++u)
            accum2(a0, a1, in_buf, k0 + kk + u, packdup(w[u].x), packdup(w[u].y));
        #pragma unroll
        for (int u = 0; u < 4; ++u) w[u] = wn[u];
    }
    #pragma unroll
    for (int u = 0; u < 4; ++u)
        accum2(a0, a1, in_buf, k0 + KS - 4 + u, packdup(w[u].x), packdup(w[u].y));
    #pragma unroll
    for (int p = 0; p < 4; ++p) { unpack2(a0[p], v0[2*p], v0[2*p+1]); unpack2(a1[p], v1[2*p], v1[2*p+1]); }
}

// warp-level reduce of 8 per-row partials; lane 0 holds sums
__device__ __forceinline__ void warp_reduce8(float sq[8]) {
    #pragma unroll
    for (int off = 16; off > 0; off >>= 1) {
        #pragma unroll
        for (int m = 0; m < 8; ++m)
            sq[m] += __shfl_down_sync(0xffffffffu, sq[m], off);
    }
}

__global__ void __launch_bounds__(NTHR, 2)
node_kernel(const float* __restrict__ y0, const float* __restrict__ tv,
            const float* __restrict__ noise,
            const float* __restrict__ fw1, const float* __restrict__ fb1,
            const float* __restrict__ fw2, const float* __restrict__ fb2,
            const float* __restrict__ fw3, const float* __restrict__ fb3,
            const float* __restrict__ amw1, const float* __restrict__ amb1,
            const float* __restrict__ amw2, const float* __restrict__ amb2,
            const float* __restrict__ amw3, const float* __restrict__ amb3,
            const float* __restrict__ alw1, const float* __restrict__ alb1,
            const float* __restrict__ alw2, const float* __restrict__ alb2,
            const float* __restrict__ alw3, const float* __restrict__ alb3,
            const float* __restrict__ kw, float* __restrict__ out)
{
    extern __shared__ float smem[];
    float* xs   = smem;              // 1024  [128][8]
    float* h1   = xs + 1024;         // 2048  [256][8]
    float* h2   = h1 + 2048;         // 2048
    float* fo   = h2 + 2048;         // 1024
    float* ko   = fo + 1024;         // 1024
    float* mo   = ko + 1024;         // 1024
    float* lso  = mo + 1024;         // 1024
    float* go   = lso + 1024;        // 1024  (f+g)
    float* ubf  = go + 1024;         // 1024
    float* ubg  = ubf + 1024;        // 1024
    float* a1m  = ubg + 1024;        // 512   [64][8]
    float* a1l  = a1m + 512;         // 512
    float* a2m  = a1l + 512;         // 512
    float* a2l  = a2m + 512;         // 512
    float* cb   = a2l + 512;         // 4096  partial scratch [512][8]
    float* redk = cb + 4096;         // 16
    float* redf = redk + 16;         // 32
    float* redg = redf + 32;         // 32
    float* kn2s = redg + 32;         // 8

    const int tid = threadIdx.x;
    const int r0 = blockIdx.x * MROWS;
    const float dt = tv[1] - tv[0];
    const int ewj = tid & 127;       // elementwise: col j
    const int ewc = tid >> 7;        // elementwise: chunk c (0/1), rows 4c..4c+3

    // load y0 tile (transposed [128][8]); emit output step 0
    {
        float a[4];
        #pragma unroll
        for (int q = 0; q < 4; ++q) {
            int m = 4 * ewc + q;
            float val = y0[(size_t)(r0 + m) * ND + ewj];
            out[(size_t)(r0 + m) * ND + ewj] = val;
            a[q] = val;
        }
        reinterpret_cast<float4*>(xs + ewj * 8)[ewc] = make_float4(a[0], a[1], a[2], a[3]);
    }
    __syncthreads();

    for (int step = 0; step < NSTEPS; ++step) {
        float v0[8], v1[8];
        // noise prefetch (consumed in stage E)
        float nse[4];
        {
            const float* np = noise + (size_t)step * BSZ * ND + (size_t)(r0 + 4 * ewc) * ND + ewj;
            #pragma unroll
            for (int q = 0; q < 4; ++q) nse[q] = np[(size_t)q * ND];
        }

        // ======== Stage A: f1(128thr,2col) || k(64thr,2col) || am1(32thr,2col) || al1(32thr,2col) ========
        if (tid < 128) {
            int j2 = 2 * tid;
            gaccum2(v0, v1, xs, fw1, HID, j2, 0, ND);
            float2 b = reinterpret_cast<const float2*>(fb1)[tid];
            #pragma unroll
            for (int m = 0; m < 8; ++m) { v0[m] = fast_tanh(v0[m] + b.x); v1[m] = fast_tanh(v1[m] + b.y); }
            store_row8(h1, j2, v0); store_row8(h1, j2 + 1, v1);
        } else if (tid < 192) {
            int t = tid - 128, j2 = 2 * t;
            gaccum2(v0, v1, xs, kw, ND, j2, 0, ND);
            float sq[8];
            #pragma unroll
            for (int m = 0; m < 8; ++m) {
                v0[m] = fast_tanh(v0[m]); v1[m] = fast_tanh(v1[m]);
                sq[m] = v0[m] * v0[m] + v1[m] * v1[m];
            }
            store_row8(ko, j2, v0); store_row8(ko, j2 + 1, v1);
            warp_reduce8(sq);
            if ((tid & 31) == 0) {
                int w = (tid - 128) >> 5;
                #pragma unroll
                for (int m = 0; m < 8; ++m) redk[w * 8 + m] = sq[m];
            }
        } else if (tid < 224) {
            int t = tid - 192, j2 = 2 * t;
            gaccum2(v0, v1, xs, amw1, SHD, j2, 0, ND);
            float2 b = reinterpret_cast<const float2*>(amb1)[t];
            #pragma unroll
            for (int m = 0; m < 8; ++m) { v0[m] = fmaxf(v0[m] + b.x, 0.f); v1[m] = fmaxf(v1[m] + b.y, 0.f); }
            store_row8(a1m, j2, v0); store_row8(a1m, j2 + 1, v1);
        } else {
            int t = tid - 224, j2 = 2 * t;
            gaccum2(v0, v1, xs, alw1, SHD, j2, 0, ND);
            float2 b = reinterpret_cast<const float2*>(alb1)[t];
            #pragma unroll
            for (int m = 0; m < 8; ++m) { v0[m] = fmaxf(v0[m] + b.x, 0.f); v1[m] = fmaxf(v1[m] + b.y, 0.f); }
            store_row8(a1l, j2, v0); store_row8(a1l, j2 + 1, v1);
        }
        __syncthreads();

        // ======== Stage B: f2 (2 cols/thread, K split over 2 halves) — r9 proven ========
        {
            int t = tid & 127, s = tid >> 7, j2 = 2 * t;
            gaccum2(v0, v1, h1, fw2, HID, j2, s * 128, 128);
            if (s == 1) { store_row8(cb, j2, v0); store_row8(cb, j2 + 1, v1); }
        }
        __syncthreads();

        // ======== Stage B2: h2 combine + softplus (s==0 threads, carried v0/v1); kn2s ========
        {
            int t = tid & 127, s = tid >> 7, j2 = 2 * t;
            if (s == 0) {
                float w0[8], w1[8];
                load_row8(cb, j2, w0); load_row8(cb, j2 + 1, w1);
                float2 b = reinterpret_cast<const float2*>(fb2)[t];
                #pragma unroll
                for (int m = 0; m < 8; ++m) {
                    v0[m] = fast_softplus(v0[m] + w0[m] + b.x);
                    v1[m] = fast_softplus(v1[m] + w1[m] + b.y);
                }
                store_row8(h2, j2, v0); store_row8(h2, j2 + 1, v1);
            }
            if (tid < 8) kn2s[tid] = redk[tid] + redk[8 + tid];
        }
        __syncthreads();

        // ======== Stage C1: f3 — 2-col x 4 K-splits over all 256 thr; ALL slices to cb ========
        {
            int cg = tid >> 2, s = tid & 3, j2 = 2 * cg;
            gaccum2(v0, v1, h2, fw3, ND, j2, s * 64, 64);
            store_row8(cb, s * 128 + j2, v0);
            store_row8(cb, s * 128 + j2 + 1, v1);
        }
        __syncthreads();

        // ======== Stage C2: f3 combine (128thr,1col) || am2 (32thr,2col) || al2 (32thr,2col) ========
        if (tid < 128) {
            float acc8[8], t8[8];
            load_row8(cb, tid, acc8);
            #pragma unroll
            for (int s = 1; s < 4; ++s) {
                load_row8(cb, s * 128 + tid, t8);
                #pragma unroll
                for (int m = 0; m < 8; ++m) acc8[m] += t8[m];
            }
            float b = fb3[tid];
            #pragma unroll
            for (int m = 0; m < 8; ++m) acc8[m] += b;
            store_row8(fo, tid, acc8);
        } else if (tid < 160) {
            int t = tid - 128, j2 = 2 * t;     // am2: 64 cols over 32 thr
            gaccum2(v0, v1, a1m, amw2, SHD, j2, 0, SHD);
            float2 b = reinterpret_cast<const float2*>(amb2)[t];
            #pragma unroll
            for (int m = 0; m < 8; ++m) { v0[m] = fmaxf(v0[m] + b.x, 0.f); v1[m] = fmaxf(v1[m] + b.y, 0.f); }
            store_row8(a2m, j2, v0); store_row8(a2m, j2 + 1, v1);
        } else if (tid < 192) {
            int t = tid - 160, j2 = 2 * t;     // al2
            gaccum2(v0, v1, a1l, alw2, SHD, j2, 0, SHD);
            float2 b = reinterpret_cast<const float2*>(alb2)[t];
            #pragma unroll
            for (int m = 0; m < 8; ++m) { v0[m] = fmaxf(v0[m] + b.x, 0.f); v1[m] = fmaxf(v1[m] + b.y, 0.f); }
            store_row8(a2l, j2, v0); store_row8(a2l, j2 + 1, v1);
        }
        __syncthreads();

        // ======== Stage C3: am3 (64thr,2col) || al3 (64thr,2col) ========
        if (tid < 64) {
            int j2 = 2 * tid;                  // am3: 128 cols over 64 thr
            gaccum2(v0, v1, a2m, amw3, ND, j2, 0, SHD);
            float2 b = reinterpret_cast<const float2*>(amb3)[tid];
            #pragma unroll
            for (int m = 0; m < 8; ++m) { v0[m] = fast_tanh(v0[m] + b.x); v1[m] = fast_tanh(v1[m] + b.y); }
            store_row8(mo, j2, v0); store_row8(mo, j2 + 1, v1);
        } else if (tid < 128) {
            int t = tid - 64, j2 = 2 * t;      // al3
            gaccum2(v0, v1, a2l, alw3, ND, j2, 0, SHD);
            float2 b = reinterpret_cast<const float2*>(alb3)[t];
            #pragma unroll
            for (int m = 0; m < 8; ++m) { v0[m] += b.x; v1[m] += b.y; }
            store_row8(lso, j2, v0); store_row8(lso, j2 + 1, v1);
        }
        __syncthreads();

        // ======== Stage E: g, f+g, u_f, u_g (elementwise float4) ========
        {
            float4 kv = reinterpret_cast<const float4*>(ko + ewj * 8)[ewc];
            float4 fv = reinterpret_cast<const float4*>(fo + ewj * 8)[ewc];
            float4 mv = reinterpret_cast<const float4*>(mo + ewj * 8)[ewc];
            float4 lv = reinterpret_cast<const float4*>(lso + ewj * 8)[ewc];
            float kk[4] = {kv.x, kv.y, kv.z, kv.w};
            float ff[4] = {fv.x, fv.y, fv.z, fv.w};
            float mm[4] = {mv.x, mv.y, mv.z, mv.w};
            float ll[4] = {lv.x, lv.y, lv.z, lv.w};
            float gs[4], uf[4], ug[4];
            #pragma unroll
            for (int q = 0; q < 4; ++q) {
                float sd = fast_softplus(san(ll[q]));
                float g = fast_tanh(san(mm[q]) + sd * nse[q]);
                float om = 1.f - kk[q] * kk[q];
                gs[q] = ff[q] + g;
                uf[q] = om * ff[q];
                ug[q] = om * g;
            }
            reinterpret_cast<float4*>(go + ewj * 8)[ewc] = make_float4(gs[0], gs[1], gs[2], gs[3]);
            reinterpret_cast<float4*>(ubf + ewj * 8)[ewc] = make_float4(uf[0], uf[1], uf[2], uf[3]);
            reinterpret_cast<float4*>(ubg + ewj * 8)[ewc] = make_float4(ug[0], ug[1], ug[2], ug[3]);
        }
        __syncthreads();

        // ======== Stage F: jacf (128thr, 2col x 2ks) || jacg (128thr, 2col x 2ks); ALL to cb ========
        if (tid < 128) {
            int cg = tid >> 1, s = tid & 1, j2 = 2 * cg;
            gaccum2(v0, v1, ubf, kw, ND, j2, s * 64, 64);
            store_row8(cb, s * 256 + j2, v0); store_row8(cb, s * 256 + j2 + 1, v1);
        } else {
            int t = tid - 128, cg = t >> 1, s = t & 1, j2 = 2 * cg;
            gaccum2(v0, v1, ubg, kw, ND, j2, s * 64, 64);
            store_row8(cb, s * 256 + 128 + j2, v0); store_row8(cb, s * 256 + 128 + j2 + 1, v1);
        }
        __syncthreads();

        // ======== Stage F2: combine + reduce (conflict-free consecutive-row loads) ========
        if (tid < 128) {
            float va[8], wa[8];
            load_row8(cb, tid, va); load_row8(cb, 256 + tid, wa);
            float sq[8];
            #pragma unroll
            for (int m = 0; m < 8; ++m) { float x = va[m] + wa[m]; sq[m] = x * x; }
            warp_reduce8(sq);
            if ((tid & 31) == 0) {
                int w = tid >> 5;
                #pragma unroll
                for (int m = 0; m < 8; ++m) redf[w * 8 + m] = sq[m];
            }
        } else {
            int col = tid - 128;
            float va[8], wa[8], kr[8];
            load_row8(cb, 128 + col, va); load_row8(cb, 384 + col, wa);
            load_row8(ko, col, kr);
            float sq[8];
            #pragma unroll
            for (int m = 0; m < 8; ++m) sq[m] = (va[m] + wa[m]) * kr[m];
            warp_reduce8(sq);
            if ((tid & 31) == 0) {
                int w = (tid - 128) >> 5;
                #pragma unroll
                for (int m = 0; m < 8; ++m) redg[w * 8 + m] = sq[m];
            }
        }
        __syncthreads();

        // ======== Update: inline mask + Euler + output ========
        {
            float sclq[4];
            #pragma unroll
            for (int q = 0; q < 4; ++q) {
                int m = 4 * ewc + q;
                float kn2 = kn2s[m];
                float jf2 = redf[m] + redf[8 + m] + redf[16 + m] + redf[24 + m];
                float c2v = redg[m] + redg[8 + m] + redg[16 + m] + redg[24 + m];
                float kn = sqrtf(kn2);
                float kn9 = kn2 * kn2 * kn2 * kn2 * kn;
                float c1 = sqrtf(jf2) - 60.0f * kn9;
                float c2 = c2v - 20.0f * kn9 * kn;
                bool mask = (c1 > 1e-8f) || (c2 < -1e-8f);
                sclq[q] = mask ? (0.5f * dt) : dt;
            }
            float4 xv = reinterpret_cast<const float4*>(xs + ewj * 8)[ewc];
            float4 dv = reinterpret_cast<const float4*>(go + ewj * 8)[ewc];
            float x[4] = {xv.x, xv.y, xv.z, xv.w};
            float d[4] = {dv.x, dv.y, dv.z, dv.w};
            float o[4];
            float* ob = out + (size_t)(step + 1) * BSZ * ND;
            #pragma unroll
            for (int q = 0; q < 4; ++q) {
                int m = 4 * ewc + q;
                o[q] = x[q] + d[q] * sclq[q];
                ob[(size_t)(r0 + m) * ND + ewj] = o[q];
            }
            reinterpret_cast<float4*>(xs + ewj * 8)[ewc] = make_float4(o[0], o[1], o[2], o[3]);
        }
        __syncthreads();
    }
}

extern "C" void kernel_launch(void* const* d_in, const int* in_sizes, int n_in,
                              void* d_out, int out_size) {
    (void)in_sizes; (void)n_in; (void)out_size;
    const float* y0   = (const float*)d_in[0];
    const float* tv   = (const float*)d_in[1];
    const float* nz   = (const float*)d_in[2];
    const float* fw1  = (const float*)d_in[3];
    const float* fb1  = (const float*)d_in[4];
    const float* fw2  = (const float*)d_in[5];
    const float* fb2  = (const float*)d_in[6];
    const float* fw3  = (const float*)d_in[7];
    const float* fb3  = (const float*)d_in[8];
    const float* amw1 = (const float*)d_in[9];
    const float* amb1 = (const float*)d_in[10];
    const float* amw2 = (const float*)d_in[11];
    const float* amb2 = (const float*)d_in[12];
    const float* amw3 = (const float*)d_in[13];
    const float* amb3 = (const float*)d_in[14];
    const float* alw1 = (const float*)d_in[15];
    const float* alb1 = (const float*)d_in[16];
    const float* alw2 = (const float*)d_in[17];
    const float* alb2 = (const float*)d_in[18];
    const float* alw3 = (const float*)d_in[19];
    const float* alb3 = (const float*)d_in[20];
    const float* kw   = (const float*)d_in[21];
    float* out = (float*)d_out;

    const int shmem = 18520 * sizeof(float);  // ~74.1 KB -> 2 blocks/SM
    cudaFuncSetAttribute(node_kernel, cudaFuncAttributeMaxDynamicSharedMemorySize, shmem);
    node_kernel<<<NBLOCKS, NTHR, shmem>>>(
        y0, tv, nz, fw1, fb1, fw2, fb2, fw3, fb3,
        amw1, amb1, amw2, amb2, amw3, amb3,
        alw1, alb1, alw2, alb2, alw3, alb3, kw, out);
}

// round 13
// speedup vs baseline: 1.6394x; 1.5949x over previous
#include <cuda_runtime.h>
#include <math.h>

#define BSZ 2048
#define ND 128
#define HID 256
#define SHD 64
#define NSTEPS 8
#define MROWS 8
#define NBLOCKS (BSZ / MROWS)
#define NTHR 256

typedef unsigned long long ull;

// ---------- packed f32x2 helpers ----------
__device__ __forceinline__ void fma2(ull &c, ull a, ull b) {
    asm("fma.rn.f32x2 %0, %1, %2, %3;" : "=l"(c) : "l"(a), "l"(b), "l"(c));
}
__device__ __forceinline__ ull packdup(float x) {
    ull r; asm("mov.b64 %0, {%1, %2};" : "=l"(r) : "f"(x), "f"(x)); return r;
}
__device__ __forceinline__ void unpack2(ull v, float &x, float &y) {
    asm("mov.b64 {%0, %1}, %2;" : "=f"(x), "=f"(y) : "l"(v));
}

// ---------- swizzled 16B-chunk shared layout ----------
// Buffer = [rows][8 floats]; chunk ci = row*2 + half. Physical slot = ci ^ ((ci>>3)&7).
// Permutes within 64-chunk blocks; all buffers are multiples of 32 rows.
#define CSW(ci) ((ci) ^ (((ci) >> 3) & 7))
__device__ __forceinline__ ulonglong2 ldchunk_u(const float* buf, int ci) {
    return reinterpret_cast<const ulonglong2*>(buf)[CSW(ci)];
}
__device__ __forceinline__ float4 ldchunk_f(const float* buf, int ci) {
    return reinterpret_cast<const float4*>(buf)[CSW(ci)];
}
__device__ __forceinline__ void stchunk_f(float* buf, int ci, float4 v) {
    reinterpret_cast<float4*>(buf)[CSW(ci)] = v;
}
__device__ __forceinline__ void load_row8(const float* buf, int r, float v[8]) {
    float4 c0 = ldchunk_f(buf, 2 * r);
    float4 c1 = ldchunk_f(buf, 2 * r + 1);
    v[0]=c0.x; v[1]=c0.y; v[2]=c0.z; v[3]=c0.w;
    v[4]=c1.x; v[5]=c1.y; v[6]=c1.z; v[7]=c1.w;
}
__device__ __forceinline__ void store_row8(float* buf, int r, const float v[8]) {
    stchunk_f(buf, 2 * r,     make_float4(v[0], v[1], v[2], v[3]));
    stchunk_f(buf, 2 * r + 1, make_float4(v[4], v[5], v[6], v[7]));
}

// ---------- fast transcendentals ----------
__device__ __forceinline__ float fast_tanh(float x) {
    float z = __expf(2.0f * x);
    return 1.0f - 2.0f / (z + 1.0f);
}
__device__ __forceinline__ float fast_softplus(float x) {
    float z = __expf(-fabsf(x));
    return fmaxf(x, 0.0f) + __logf(1.0f + z);
}
__device__ __forceinline__ float san(float x) { return isfinite(x) ? x : 0.f; }

// ---------- 4-col x 4-row accumulate: one 16B LDS feeds 8 fma2 ----------
__device__ __forceinline__ void acc44(ull acc[8], const float* in_buf, int k, int h, float4 wv) {
    ulonglong2 p = ldchunk_u(in_buf, 2 * k + h);
    fma2(acc[0], p.x, packdup(wv.x)); fma2(acc[1], p.y, packdup(wv.x));
    fma2(acc[2], p.x, packdup(wv.y)); fma2(acc[3], p.y, packdup(wv.y));
    fma2(acc[4], p.x, packdup(wv.z)); fma2(acc[5], p.y, packdup(wv.z));
    fma2(acc[6], p.x, packdup(wv.w)); fma2(acc[7], p.y, packdup(wv.w));
}

// 4-col x 4-row GEMM partial: cols j4..j4+3, rows 4h..4h+3, float4 weights, 4-deep prefetch.
// v layout: v[c*4 + q] = (col j4+c, row 4h+q). KS multiple of 4, >= 8.
__device__ __forceinline__ void gaccum44(float v[16], const float* in_buf,
                                         const float* __restrict__ W, int ldw,
                                         int j4, int h, int k0, int KS) {
    ull acc[8];
    #pragma unroll
    for (int p = 0; p < 8; ++p) acc[p] = 0ULL;
    const int wld4 = ldw >> 2;
    const float4* __restrict__ wp = reinterpret_cast<const float4*>(W) + (size_t)k0 * wld4 + (j4 >> 2);
    float4 w[4];
    #pragma unroll
    for (int u = 0; u < 4; ++u) w[u] = wp[(size_t)u * wld4];
    wp += (size_t)4 * wld4;
    for (int kk = 0; kk < KS - 4; kk += 4) {
        float4 wn[4];
        #pragma unroll
        for (int u = 0; u < 4; ++u) wn[u] = wp[(size_t)u * wld4];
        wp += (size_t)4 * wld4;
        #pragma unroll
        for (int u = 0; u < 4; ++u) acc44(acc, in_buf, k0 + kk + u, h, w[u]);
        #pragma unroll
        for (int u = 0; u < 4; ++u) w[u] = wn[u];
    }
    #pragma unroll
    for (int u = 0; u < 4; ++u) acc44(acc, in_buf, k0 + KS - 4 + u, h, w[u]);
    #pragma unroll
    for (int c = 0; c < 4; ++c) {
        unpack2(acc[2*c],     v[c*4+0], v[c*4+1]);
        unpack2(acc[2*c + 1], v[c*4+2], v[c*4+3]);
    }
}

// store 4 cols' half-chunks: col j4+c, half h <- v[c*4..c*4+3]
__device__ __forceinline__ void store4(float* buf, int jbase, int h, const float v[16]) {
    #pragma unroll
    for (int c = 0; c < 4; ++c)
        stchunk_f(buf, (jbase + c) * 2 + h, make_float4(v[c*4+0], v[c*4+1], v[c*4+2], v[c*4+3]));
}

// ---------- 1-col GEMM partial (small stages), swizzle-aware, 4-deep prefetch ----------
__device__ __forceinline__ void accum1(ull a[4], const float* in_buf, int k, ull w2) {
    ulonglong2 p0 = ldchunk_u(in_buf, 2 * k);
    ulonglong2 p1 = ldchunk_u(in_buf, 2 * k + 1);
    fma2(a[0], p0.x, w2); fma2(a[1], p0.y, w2);
    fma2(a[2], p1.x, w2); fma2(a[3], p1.y, w2);
}
__device__ __forceinline__ void gaccum1(float v[8], const float* in_buf,
                                        const float* __restrict__ W, int ldw,
                                        int j, int k0, int KS) {
    ull a[4];
    #pragma unroll
    for (int p = 0; p < 4; ++p) a[p] = 0ULL;
    const float* __restrict__ wp = W + (size_t)k0 * ldw + j;
    float w[4];
    #pragma unroll
    for (int u = 0; u < 4; ++u) w[u] = wp[(size_t)u * ldw];
    wp += (size_t)4 * ldw;
    for (int kk = 0; kk < KS - 4; kk += 4) {
        float wn[4];
        #pragma unroll
        for (int u = 0; u < 4; ++u) wn[u] = wp[(size_t)u * ldw];
        wp += (size_t)4 * ldw;
        #pragma unroll
        for (int u = 0; u < 4; ++u) accum1(a, in_buf, k0 + kk + u, packdup(w[u]));
        #pragma unroll
        for (int u = 0; u < 4; ++u) w[u] = wn[u];
    }
    #pragma unroll
    for (int u = 0; u < 4; ++u) accum1(a, in_buf, k0 + KS - 4 + u, packdup(w[u]));
    #pragma unroll
    for (int p = 0; p < 4; ++p) unpack2(a[p], v[2*p], v[2*p+1]);
}

// warp-level reduce of 8 per-row partials; lane 0 holds sums
__device__ __forceinline__ void warp_reduce8(float sq[8]) {
    #pragma unroll
    for (int off = 16; off > 0; off >>= 1) {
        #pragma unroll
        for (int m = 0; m < 8; ++m)
            sq[m] += __shfl_down_sync(0xffffffffu, sq[m], off);
    }
}

__global__ void __launch_bounds__(NTHR, 2)
node_kernel(const float* __restrict__ y0, const float* __restrict__ tv,
            const float* __restrict__ noise,
            const float* __restrict__ fw1, const float* __restrict__ fb1,
            const float* __restrict__ fw2, const float* __restrict__ fb2,
            const float* __restrict__ fw3, const float* __restrict__ fb3,
            const float* __restrict__ amw1, const float* __restrict__ amb1,
            const float* __restrict__ amw2, const float* __restrict__ amb2,
            const float* __restrict__ amw3, const float* __restrict__ amb3,
            const float* __restrict__ alw1, const float* __restrict__ alb1,
            const float* __restrict__ alw2, const float* __restrict__ alb2,
            const float* __restrict__ alw3, const float* __restrict__ alb3,
            const float* __restrict__ kw, float* __restrict__ out)
{
    extern __shared__ float smem[];
    float* xs   = smem;              // 1024  [128][8]
    float* h1   = xs + 1024;         // 2048  [256][8]
    float* h2   = h1 + 2048;         // 2048
    float* fo   = h2 + 2048;         // 1024
    float* ko   = fo + 1024;         // 1024
    float* mo   = ko + 1024;         // 1024
    float* lso  = mo + 1024;         // 1024
    float* go   = lso + 1024;        // 1024  (f+g)
    float* ubf  = go + 1024;         // 1024
    float* ubg  = ubf + 1024;        // 1024
    float* a1m  = ubg + 1024;        // 512   [64][8]
    float* a1l  = a1m + 512;         // 512
    float* a2m  = a1l + 512;         // 512
    float* a2l  = a2m + 512;         // 512
    float* cb   = a2l + 512;         // 4096  partial scratch [512][8]
    float* redk = cb + 4096;         // 16
    float* redf = redk + 16;         // 32
    float* redg = redf + 32;         // 32
    float* kn2s = redg + 32;         // 8

    const int tid = threadIdx.x;
    const int r0 = blockIdx.x * MROWS;
    const float dt = tv[1] - tv[0];
    const int ewj = tid & 127;       // elementwise: col j
    const int ewc = tid >> 7;        // elementwise: half (rows 4c..4c+3)

    // load y0 tile (transposed [128][8], swizzled); emit output step 0
    {
        float a[4];
        #pragma unroll
        for (int q = 0; q < 4; ++q) {
            int m = 4 * ewc + q;
            float val = y0[(size_t)(r0 + m) * ND + ewj];
            out[(size_t)(r0 + m) * ND + ewj] = val;
            a[q] = val;
        }
        stchunk_f(xs, ewj * 2 + ewc, make_float4(a[0], a[1], a[2], a[3]));
    }
    __syncthreads();

    for (int step = 0; step < NSTEPS; ++step) {
        float v[16];
        float nse[4];
        {
            const float* np = noise + (size_t)step * BSZ * ND + (size_t)(r0 + 4 * ewc) * ND + ewj;
            #pragma unroll
            for (int q = 0; q < 4; ++q) nse[q] = np[(size_t)q * ND];
        }

        // ======== Stage A: f1(128t) || k(64t) || am1(32t) || al1(32t), 4col x 4row, full K ========
        if (tid < 128) {                       // f1 -> h1 (256 cols: 64 cg x 2 h)
            int h = tid & 1, cg = tid >> 1, j4 = 4 * cg;
            gaccum44(v, xs, fw1, HID, j4, h, 0, ND);
            float4 b = reinterpret_cast<const float4*>(fb1)[cg];
            float bb[4] = {b.x, b.y, b.z, b.w};
            #pragma unroll
            for (int c = 0; c < 4; ++c)
                #pragma unroll
                for (int q = 0; q < 4; ++q) v[c*4+q] = fast_tanh(v[c*4+q] + bb[c]);
            store4(h1, j4, h, v);
        } else if (tid < 192) {                // k -> ko (+||k||^2 partials)
            int u = tid - 128, h = u & 1, cg = u >> 1, j4 = 4 * cg;
            gaccum44(v, xs, kw, ND, j4, h, 0, ND);
            float sq4[4] = {0.f, 0.f, 0.f, 0.f};
            #pragma unroll
            for (int c = 0; c < 4; ++c)
                #pragma unroll
                for (int q = 0; q < 4; ++q) {
                    float t = fast_tanh(v[c*4+q]);
                    v[c*4+q] = t;
                    sq4[q] += t * t;
                }
            store4(ko, j4, h, v);
            #pragma unroll
            for (int off = 16; off >= 2; off >>= 1)
                #pragma unroll
                for (int q = 0; q < 4; ++q)
                    sq4[q] += __shfl_down_sync(0xffffffffu, sq4[q], off);
            if ((tid & 31) < 2) {              // lane0 holds h=0 sums, lane1 h=1
                int w = (tid - 128) >> 5;      // warp 0/1 of the k group
                int hh = tid & 1;
                #pragma unroll
                for (int q = 0; q < 4; ++q) redk[w * 8 + hh * 4 + q] = sq4[q];
            }
        } else if (tid < 224) {                // am1 -> a1m (64 cols: 16 cg x 2 h)
            int u = tid - 192, h = u & 1, cg = u >> 1, j4 = 4 * cg;
            gaccum44(v, xs, amw1, SHD, j4, h, 0, ND);
            float4 b = reinterpret_cast<const float4*>(amb1)[cg];
            float bb[4] = {b.x, b.y, b.z, b.w};
            #pragma unroll
            for (int c = 0; c < 4; ++c)
                #pragma unroll
                for (int q = 0; q < 4; ++q) v[c*4+q] = fmaxf(v[c*4+q] + bb[c], 0.f);
            store4(a1m, j4, h, v);
        } else {                               // al1 -> a1l
            int u = tid - 224, h = u & 1, cg = u >> 1, j4 = 4 * cg;
            gaccum44(v, xs, alw1, SHD, j4, h, 0, ND);
            float4 b = reinterpret_cast<const float4*>(alb1)[cg];
            float bb[4] = {b.x, b.y, b.z, b.w};
            #pragma unroll
            for (int c = 0; c < 4; ++c)
                #pragma unroll
                for (int q = 0; q < 4; ++q) v[c*4+q] = fmaxf(v[c*4+q] + bb[c], 0.f);
            store4(a1l, j4, h, v);
        }
        __syncthreads();

        // ======== Stage B: f2, 4x4, K split over 2 warp-groups (s = tid>>7) ========
        {
            int s = tid >> 7, u2 = tid & 127, h = u2 & 1, cg = u2 >> 1, j4 = 4 * cg;
            gaccum44(v, h1, fw2, HID, j4, h, s * 128, 128);
            if (s == 1) store4(cb, j4, h, v);
        }
        __syncthreads();

        // ======== Stage B2: combine + softplus -> h2 (s==0, carried v); finish ||k||^2 ========
        {
            int s = tid >> 7, u2 = tid & 127, h = u2 & 1, cg = u2 >> 1, j4 = 4 * cg;
            if (s == 0) {
                float4 b = reinterpret_cast<const float4*>(fb2)[cg];
                float bb[4] = {b.x, b.y, b.z, b.w};
                #pragma unroll
                for (int c = 0; c < 4; ++c) {
                    float4 wc = ldchunk_f(cb, (j4 + c) * 2 + h);
                    float wq[4] = {wc.x, wc.y, wc.z, wc.w};
                    #pragma unroll
                    for (int q = 0; q < 4; ++q)
                        v[c*4+q] = fast_softplus(v[c*4+q] + wq[q] + bb[c]);
                }
                store4(h2, j4, h, v);
            }
            if (tid < 8) kn2s[tid] = redk[tid] + redk[8 + tid];
        }
        __syncthreads();

        // ======== Stage C1: f3, 4x4, 4 warp-uniform K-splits (s = tid>>6); ALL partials to cb ========
        {
            int s = tid >> 6, u = tid & 63, h = u & 1, cg = u >> 1, j4 = 4 * cg;
            gaccum44(v, h2, fw3, ND, j4, h, s * 64, 64);
            store4(cb, s * 128 + j4, h, v);
        }
        __syncthreads();

        // ======== Stage C2: f3 combine (128t) || am2 (32t, 4x4) || al2 (32t, 4x4) ========
        if (tid < 128) {
            float r8[8] = {0,0,0,0,0,0,0,0};
            #pragma unroll
            for (int s = 0; s < 4; ++s) {
                float4 c0 = ldchunk_f(cb, (s * 128 + tid) * 2);
                float4 c1 = ldchunk_f(cb, (s * 128 + tid) * 2 + 1);
                r8[0]+=c0.x; r8[1]+=c0.y; r8[2]+=c0.z; r8[3]+=c0.w;
                r8[4]+=c1.x; r8[5]+=c1.y; r8[6]+=c1.z; r8[7]+=c1.w;
            }
            float b = fb3[tid];
            #pragma unroll
            for (int m = 0; m < 8; ++m) r8[m] += b;
            store_row8(fo, tid, r8);
        } else if (tid < 160) {                // am2 -> a2m (64 cols: 16 cg x 2 h)
            int u = tid - 128, h = u & 1, cg = u >> 1, j4 = 4 * cg;
            gaccum44(v, a1m, amw2, SHD, j4, h, 0, SHD);
            float4 b = reinterpret_cast<const float4*>(amb2)[cg];
            float bb[4] = {b.x, b.y, b.z, b.w};
            #pragma unroll
            for (int c = 0; c < 4; ++c)
                #pragma unroll
                for (int q = 0; q < 4; ++q) v[c*4+q] = fmaxf(v[c*4+q] + bb[c], 0.f);
            store4(a2m, j4, h, v);
        } else if (tid < 192) {                // al2 -> a2l
            int u = tid - 160, h = u & 1, cg = u >> 1, j4 = 4 * cg;
            gaccum44(v, a1l, alw2, SHD, j4, h, 0, SHD);
            float4 b = reinterpret_cast<const float4*>(alb2)[cg];
            float bb[4] = {b.x, b.y, b.z, b.w};
            #pragma unroll
            for (int c = 0; c < 4; ++c)
                #pragma unroll
                for (int q = 0; q < 4; ++q) v[c*4+q] = fmaxf(v[c*4+q] + bb[c], 0.f);
            store4(a2l, j4, h, v);
        }
        __syncthreads();

        // ======== Stage C3: am3 (128t,1col) || al3 (128t,1col) — r9 proven shape ========
        if (tid < 128) {
            float v8[8];
            gaccum1(v8, a2m, amw3, ND, tid, 0, SHD);
            float b = amb3[tid];
            #pragma unroll
            for (int m = 0; m < 8; ++m) v8[m] = fast_tanh(v8[m] + b);
            store_row8(mo, tid, v8);
        } else {
            int j = tid - 128;
            float v8[8];
            gaccum1(v8, a2l, alw3, ND, j, 0, SHD);
            float b = alb3[j];
            #pragma unroll
            for (int m = 0; m < 8; ++m) v8[m] += b;
            store_row8(lso, j, v8);
        }
        __syncthreads();

        // ======== Stage E: g, f+g, u_f, u_g (elementwise, swizzled chunks) ========
        {
            float4 kv = ldchunk_f(ko,  ewj * 2 + ewc);
            float4 fv = ldchunk_f(fo,  ewj * 2 + ewc);
            float4 mv = ldchunk_f(mo,  ewj * 2 + ewc);
            float4 lv = ldchunk_f(lso, ewj * 2 + ewc);
            float kk[4] = {kv.x, kv.y, kv.z, kv.w};
            float ff[4] = {fv.x, fv.y, fv.z, fv.w};
            float mm[4] = {mv.x, mv.y, mv.z, mv.w};
            float ll[4] = {lv.x, lv.y, lv.z, lv.w};
            float gs[4], uf[4], ug[4];
            #pragma unroll
            for (int q = 0; q < 4; ++q) {
                float sd = fast_softplus(san(ll[q]));
                float g = fast_tanh(san(mm[q]) + sd * nse[q]);
                float om = 1.f - kk[q] * kk[q];
                gs[q] = ff[q] + g;
                uf[q] = om * ff[q];
                ug[q] = om * g;
            }
            stchunk_f(go,  ewj * 2 + ewc, make_float4(gs[0], gs[1], gs[2], gs[3]));
            stchunk_f(ubf, ewj * 2 + ewc, make_float4(uf[0], uf[1], uf[2], uf[3]));
            stchunk_f(ubg, ewj * 2 + ewc, make_float4(ug[0], ug[1], ug[2], ug[3]));
        }
        __syncthreads();

        // ======== Stage F: jacf (128t) || jacg (128t), 4x4, 2 warp-uniform K-splits ========
        if (tid < 128) {
            int s = tid >> 6, u = tid & 63, h = u & 1, cg = u >> 1, j4 = 4 * cg;
            gaccum44(v, ubf, kw, ND, j4, h, s * 64, 64);
            store4(cb, s * 128 + j4, h, v);             // rows 0-255
        } else {
            int t = tid - 128, s = t >> 6, u = t & 63, h = u & 1, cg = u >> 1, j4 = 4 * cg;
            gaccum44(v, ubg, kw, ND, j4, h, s * 64, 64);
            store4(cb, 256 + s * 128 + j4, h, v);       // rows 256-511
        }
        __syncthreads();

        // ======== Stage F2: combine + reduce ========
        if (tid < 128) {
            float va[8], wa[8];
            load_row8(cb, tid, va); load_row8(cb, 128 + tid, wa);
            float sq[8];
            #pragma unroll
            for (int m = 0; m < 8; ++m) { float x = va[m] + wa[m]; sq[m] = x * x; }
            warp_reduce8(sq);
            if ((tid & 31) == 0) {
                int w = tid >> 5;
                #pragma unroll
                for (int m = 0; m < 8; ++m) redf[w * 8 + m] = sq[m];
            }
        } else {
            int col = tid - 128;
            float va[8], wa[8], kr[8];
            load_row8(cb, 256 + col, va); load_row8(cb, 384 + col, wa);
            load_row8(ko, col, kr);
            float sq[8];
            #pragma unroll
            for (int m = 0; m < 8; ++m) sq[m] = (va[m] + wa[m]) * kr[m];
            warp_reduce8(sq);
            if ((tid & 31) == 0) {
                int w = (tid - 128) >> 5;
                #pragma unroll
                for (int m = 0; m < 8; ++m) redg[w * 8 + m] = sq[m];
            }
        }
        __syncthreads();

        // ======== Update: inline mask + Euler + output ========
        {
            float sclq[4];
            #pragma unroll
            for (int q = 0; q < 4; ++q) {
                int m = 4 * ewc + q;
                float kn2 = kn2s[m];
                float jf2 = redf[m] + redf[8 + m] + redf[16 + m] + redf[24 + m];
                float c2v = redg[m] + redg[8 + m] + redg[16 + m] + redg[24 + m];
                float kn = sqrtf(kn2);
                float kn9 = kn2 * kn2 * kn2 * kn2 * kn;
                float c1 = sqrtf(jf2) - 60.0f * kn9;
                float c2 = c2v - 20.0f * kn9 * kn;
                bool mask = (c1 > 1e-8f) || (c2 < -1e-8f);
                sclq[q] = mask ? (0.5f * dt) : dt;
            }
            float4 xv = ldchunk_f(xs, ewj * 2 + ewc);
            float4 dv = ldchunk_f(go, ewj * 2 + ewc);
            float x[4] = {xv.x, xv.y, xv.z, xv.w};
            float d[4] = {dv.x, dv.y, dv.z, dv.w};
            float o[4];
            float* ob = out + (size_t)(step + 1) * BSZ * ND;
            #pragma unroll
            for (int q = 0; q < 4; ++q) {
                int m = 4 * ewc + q;
                o[q] = x[q] + d[q] * sclq[q];
                ob[(size_t)(r0 + m) * ND + ewj] = o[q];
            }
            stchunk_f(xs, ewj * 2 + ewc, make_float4(o[0], o[1], o[2], o[3]));
        }
        __syncthreads();
    }
}

extern "C" void kernel_launch(void* const* d_in, const int* in_sizes, int n_in,
                              void* d_out, int out_size) {
    (void)in_sizes; (void)n_in; (void)out_size;
    const float* y0   = (const float*)d_in[0];
    const float* tv   = (const float*)d_in[1];
    const float* nz   = (const float*)d_in[2];
    const float* fw1  = (const float*)d_in[3];
    const float* fb1  = (const float*)d_in[4];
    const float* fw2  = (const float*)d_in[5];
    const float* fb2  = (const float*)d_in[6];
    const float* fw3  = (const float*)d_in[7];
    const float* fb3  = (const float*)d_in[8];
    const float* amw1 = (const float*)d_in[9];
    const float* amb1 = (const float*)d_in[10];
    const float* amw2 = (const float*)d_in[11];
    const float* amb2 = (const float*)d_in[12];
    const float* amw3 = (const float*)d_in[13];
    const float* amb3 = (const float*)d_in[14];
    const float* alw1 = (const float*)d_in[15];
    const float* alb1 = (const float*)d_in[16];
    const float* alw2 = (const float*)d_in[17];
    const float* alb2 = (const float*)d_in[18];
    const float* alw3 = (const float*)d_in[19];
    const float* alb3 = (const float*)d_in[20];
    const float* kw   = (const float*)d_in[21];
    float* out = (float*)d_out;

    const int shmem = 18520 * sizeof(float);  // ~74.1 KB -> 2 blocks/SM
    cudaFuncSetAttribute(node_kernel, cudaFuncAttributeMaxDynamicSharedMemorySize, shmem);
    node_kernel<<<NBLOCKS, NTHR, shmem>>>(
        y0, tv, nz, fw1, fb1, fw2, fb2, fw3, fb3,
        amw1, amb1, amw2, amb2, amw3, amb3,
        alw1, alb1, alw2, alb2, alw3, alb3, kw, out);
}

// round 14
// speedup vs baseline: 1.7265x; 1.0531x over previous
#include <cuda_runtime.h>
#include <math.h>

#define BSZ 2048
#define ND 128
#define HID 256
#define SHD 64
#define NSTEPS 8
#define MROWS 8
#define NBLOCKS (BSZ / MROWS)
#define NTHR 256

typedef unsigned long long ull;

// ---------- packed f32x2 helpers ----------
__device__ __forceinline__ void fma2(ull &c, ull a, ull b) {
    asm("fma.rn.f32x2 %0, %1, %2, %3;" : "=l"(c) : "l"(a), "l"(b), "l"(c));
}
__device__ __forceinline__ ull packdup(float x) {
    ull r; asm("mov.b64 %0, {%1, %2};" : "=l"(r) : "f"(x), "f"(x)); return r;
}
__device__ __forceinline__ void unpack2(ull v, float &x, float &y) {
    asm("mov.b64 {%0, %1}, %2;" : "=f"(x), "=f"(y) : "l"(v));
}

// ---------- swizzled 16B-chunk shared layout ----------
// Buffer = [rows][8 floats]; chunk ci = row*2 + half. Physical slot = ci ^ ((ci>>3)&7).
#define CSW(ci) ((ci) ^ (((ci) >> 3) & 7))
__device__ __forceinline__ ulonglong2 ldchunk_u(const float* buf, int ci) {
    return reinterpret_cast<const ulonglong2*>(buf)[CSW(ci)];
}
__device__ __forceinline__ float4 ldchunk_f(const float* buf, int ci) {
    return reinterpret_cast<const float4*>(buf)[CSW(ci)];
}
__device__ __forceinline__ void stchunk_f(float* buf, int ci, float4 v) {
    reinterpret_cast<float4*>(buf)[CSW(ci)] = v;
}
__device__ __forceinline__ void load_row8(const float* buf, int r, float v[8]) {
    float4 c0 = ldchunk_f(buf, 2 * r);
    float4 c1 = ldchunk_f(buf, 2 * r + 1);
    v[0]=c0.x; v[1]=c0.y; v[2]=c0.z; v[3]=c0.w;
    v[4]=c1.x; v[5]=c1.y; v[6]=c1.z; v[7]=c1.w;
}
__device__ __forceinline__ void store_row8(float* buf, int r, const float v[8]) {
    stchunk_f(buf, 2 * r,     make_float4(v[0], v[1], v[2], v[3]));
    stchunk_f(buf, 2 * r + 1, make_float4(v[4], v[5], v[6], v[7]));
}

// ---------- fast transcendentals ----------
__device__ __forceinline__ float fast_tanh(float x) {
    float z = __expf(2.0f * x);
    return 1.0f - 2.0f / (z + 1.0f);
}
__device__ __forceinline__ float fast_softplus(float x) {
    float z = __expf(-fabsf(x));
    return fmaxf(x, 0.0f) + __logf(1.0f + z);
}
__device__ __forceinline__ float san(float x) { return isfinite(x) ? x : 0.f; }

// ---------- 4-col x 4-row accumulate ----------
__device__ __forceinline__ void acc44(ull acc[8], const float* in_buf, int k, int h, float4 wv) {
    ulonglong2 p = ldchunk_u(in_buf, 2 * k + h);
    fma2(acc[0], p.x, packdup(wv.x)); fma2(acc[1], p.y, packdup(wv.x));
    fma2(acc[2], p.x, packdup(wv.y)); fma2(acc[3], p.y, packdup(wv.y));
    fma2(acc[4], p.x, packdup(wv.z)); fma2(acc[5], p.y, packdup(wv.z));
    fma2(acc[6], p.x, packdup(wv.w)); fma2(acc[7], p.y, packdup(wv.w));
}

// 4-col x 4-row GEMM partial. v[c*4+q] = (col j4+c, row 4h+q). KS mult of 4, >= 8.
__device__ __forceinline__ void gaccum44(float v[16], const float* in_buf,
                                         const float* __restrict__ W, int ldw,
                                         int j4, int h, int k0, int KS) {
    ull acc[8];
    #pragma unroll
    for (int p = 0; p < 8; ++p) acc[p] = 0ULL;
    const int wld4 = ldw >> 2;
    const float4* __restrict__ wp = reinterpret_cast<const float4*>(W) + (size_t)k0 * wld4 + (j4 >> 2);
    float4 w[4];
    #pragma unroll
    for (int u = 0; u < 4; ++u) w[u] = wp[(size_t)u * wld4];
    wp += (size_t)4 * wld4;
    for (int kk = 0; kk < KS - 4; kk += 4) {
        float4 wn[4];
        #pragma unroll
        for (int u = 0; u < 4; ++u) wn[u] = wp[(size_t)u * wld4];
        wp += (size_t)4 * wld4;
        #pragma unroll
        for (int u = 0; u < 4; ++u) acc44(acc, in_buf, k0 + kk + u, h, w[u]);
        #pragma unroll
        for (int u = 0; u < 4; ++u) w[u] = wn[u];
    }
    #pragma unroll
    for (int u = 0; u < 4; ++u) acc44(acc, in_buf, k0 + KS - 4 + u, h, w[u]);
    #pragma unroll
    for (int c = 0; c < 4; ++c) {
        unpack2(acc[2*c],     v[c*4+0], v[c*4+1]);
        unpack2(acc[2*c + 1], v[c*4+2], v[c*4+3]);
    }
}
__device__ __forceinline__ void store4(float* buf, int jbase, int h, const float v[16]) {
    #pragma unroll
    for (int c = 0; c < 4; ++c)
        stchunk_f(buf, (jbase + c) * 2 + h, make_float4(v[c*4+0], v[c*4+1], v[c*4+2], v[c*4+3]));
}

// ---------- 8-col x 4-row accumulate (one 16B LDS feeds 16 fma2) ----------
__device__ __forceinline__ void acc84(ull acc[16], const float* in_buf, int k, int h,
                                      float4 wa, float4 wb) {
    ulonglong2 p = ldchunk_u(in_buf, 2 * k + h);
    fma2(acc[0],  p.x, packdup(wa.x)); fma2(acc[1],  p.y, packdup(wa.x));
    fma2(acc[2],  p.x, packdup(wa.y)); fma2(acc[3],  p.y, packdup(wa.y));
    fma2(acc[4],  p.x, packdup(wa.z)); fma2(acc[5],  p.y, packdup(wa.z));
    fma2(acc[6],  p.x, packdup(wa.w)); fma2(acc[7],  p.y, packdup(wa.w));
    fma2(acc[8],  p.x, packdup(wb.x)); fma2(acc[9],  p.y, packdup(wb.x));
    fma2(acc[10], p.x, packdup(wb.y)); fma2(acc[11], p.y, packdup(wb.y));
    fma2(acc[12], p.x, packdup(wb.z)); fma2(acc[13], p.y, packdup(wb.z));
    fma2(acc[14], p.x, packdup(wb.w)); fma2(acc[15], p.y, packdup(wb.w));
}

// 8-col x 4-row GEMM partial, depth-2 prefetch. v[c*4+q], c=0..7. KS mult of 2, >= 4.
__device__ __forceinline__ void gaccum84(float v[32], const float* in_buf,
                                         const float* __restrict__ W, int ldw,
                                         int j8, int h, int k0, int KS) {
    ull acc[16];
    #pragma unroll
    for (int p = 0; p < 16; ++p) acc[p] = 0ULL;
    const int wld4 = ldw >> 2;
    const float4* __restrict__ wp = reinterpret_cast<const float4*>(W) + (size_t)k0 * wld4 + (j8 >> 2);
    float4 wa[2], wb[2];
    #pragma unroll
    for (int u = 0; u < 2; ++u) { wa[u] = wp[(size_t)u * wld4]; wb[u] = wp[(size_t)u * wld4 + 1]; }
    wp += (size_t)2 * wld4;
    for (int kk = 0; kk < KS - 2; kk += 2) {
        float4 na[2], nb[2];
        #pragma unroll
        for (int u = 0; u < 2; ++u) { na[u] = wp[(size_t)u * wld4]; nb[u] = wp[(size_t)u * wld4 + 1]; }
        wp += (size_t)2 * wld4;
        #pragma unroll
        for (int u = 0; u < 2; ++u) acc84(acc, in_buf, k0 + kk + u, h, wa[u], wb[u]);
        #pragma unroll
        for (int u = 0; u < 2; ++u) { wa[u] = na[u]; wb[u] = nb[u]; }
    }
    #pragma unroll
    for (int u = 0; u < 2; ++u) acc84(acc, in_buf, k0 + KS - 2 + u, h, wa[u], wb[u]);
    #pragma unroll
    for (int c = 0; c < 8; ++c) {
        unpack2(acc[2*c],     v[c*4+0], v[c*4+1]);
        unpack2(acc[2*c + 1], v[c*4+2], v[c*4+3]);
    }
}
__device__ __forceinline__ void store8(float* buf, int jbase, int h, const float v[32]) {
    #pragma unroll
    for (int c = 0; c < 8; ++c)
        stchunk_f(buf, (jbase + c) * 2 + h, make_float4(v[c*4+0], v[c*4+1], v[c*4+2], v[c*4+3]));
}

// ---------- 1-col GEMM partial (kept for fallback use) ----------
__device__ __forceinline__ void warp_reduce8(float sq[8]) {
    #pragma unroll
    for (int off = 16; off > 0; off >>= 1) {
        #pragma unroll
        for (int m = 0; m < 8; ++m)
            sq[m] += __shfl_down_sync(0xffffffffu, sq[m], off);
    }
}

__global__ void __launch_bounds__(NTHR, 2)
node_kernel(const float* __restrict__ y0, const float* __restrict__ tv,
            const float* __restrict__ noise,
            const float* __restrict__ fw1, const float* __restrict__ fb1,
            const float* __restrict__ fw2, const float* __restrict__ fb2,
            const float* __restrict__ fw3, const float* __restrict__ fb3,
            const float* __restrict__ amw1, const float* __restrict__ amb1,
            const float* __restrict__ amw2, const float* __restrict__ amb2,
            const float* __restrict__ amw3, const float* __restrict__ amb3,
            const float* __restrict__ alw1, const float* __restrict__ alb1,
            const float* __restrict__ alw2, const float* __restrict__ alb2,
            const float* __restrict__ alw3, const float* __restrict__ alb3,
            const float* __restrict__ kw, float* __restrict__ out)
{
    extern __shared__ float smem[];
    float* xs   = smem;              // 1024  [128][8]
    float* h1   = xs + 1024;         // 2048  [256][8]
    float* h2   = h1 + 2048;         // 2048
    float* fo   = h2 + 2048;         // 1024
    float* ko   = fo + 1024;         // 1024
    float* go   = ko + 1024;         // 1024  (f+g)
    float* ubf  = go + 1024;         // 1024
    float* ubg  = ubf + 1024;        // 1024
    float* a1m  = ubg + 1024;        // 512   [64][8]
    float* a1l  = a1m + 512;         // 512
    float* a2m  = a1l + 512;         // 512
    float* a2l  = a2m + 512;         // 512
    float* cb   = a2l + 512;         // 8192  partial scratch [1024][8]
    float* redk = cb + 8192;         // 16
    float* redf = redk + 16;         // 32
    float* redg = redf + 32;         // 32
    float* kn2s = redg + 32;         // 8

    const int tid = threadIdx.x;
    const int r0 = blockIdx.x * MROWS;
    const float dt = tv[1] - tv[0];
    const int ewj = tid & 127;       // elementwise: col j
    const int ewc = tid >> 7;        // elementwise: half (rows 4c..4c+3)

    // load y0 tile (transposed [128][8], swizzled); emit output step 0
    {
        float a[4];
        #pragma unroll
        for (int q = 0; q < 4; ++q) {
            int m = 4 * ewc + q;
            float val = y0[(size_t)(r0 + m) * ND + ewj];
            out[(size_t)(r0 + m) * ND + ewj] = val;
            a[q] = val;
        }
        stchunk_f(xs, ewj * 2 + ewc, make_float4(a[0], a[1], a[2], a[3]));
    }
    __syncthreads();

    for (int step = 0; step < NSTEPS; ++step) {
        float v[16];
        float nse[4];
        {
            const float* np = noise + (size_t)step * BSZ * ND + (size_t)(r0 + 4 * ewc) * ND + ewj;
            #pragma unroll
            for (int q = 0; q < 4; ++q) nse[q] = np[(size_t)q * ND];
        }

        // ======== Stage A: f1(128t) || k(64t) || am1(32t) || al1(32t), 4x4, full K ========
        if (tid < 128) {
            int h = tid & 1, cg = tid >> 1, j4 = 4 * cg;
            gaccum44(v, xs, fw1, HID, j4, h, 0, ND);
            float4 b = reinterpret_cast<const float4*>(fb1)[cg];
            float bb[4] = {b.x, b.y, b.z, b.w};
            #pragma unroll
            for (int c = 0; c < 4; ++c)
                #pragma unroll
                for (int q = 0; q < 4; ++q) v[c*4+q] = fast_tanh(v[c*4+q] + bb[c]);
            store4(h1, j4, h, v);
        } else if (tid < 192) {
            int u = tid - 128, h = u & 1, cg = u >> 1, j4 = 4 * cg;
            gaccum44(v, xs, kw, ND, j4, h, 0, ND);
            float sq4[4] = {0.f, 0.f, 0.f, 0.f};
            #pragma unroll
            for (int c = 0; c < 4; ++c)
                #pragma unroll
                for (int q = 0; q < 4; ++q) {
                    float t = fast_tanh(v[c*4+q]);
                    v[c*4+q] = t;
                    sq4[q] += t * t;
                }
            store4(ko, j4, h, v);
            #pragma unroll
            for (int off = 16; off >= 2; off >>= 1)
                #pragma unroll
                for (int q = 0; q < 4; ++q)
                    sq4[q] += __shfl_down_sync(0xffffffffu, sq4[q], off);
            if ((tid & 31) < 2) {
                int w = (tid - 128) >> 5;
                int hh = tid & 1;
                #pragma unroll
                for (int q = 0; q < 4; ++q) redk[w * 8 + hh * 4 + q] = sq4[q];
            }
        } else if (tid < 224) {
            int u = tid - 192, h = u & 1, cg = u >> 1, j4 = 4 * cg;
            gaccum44(v, xs, amw1, SHD, j4, h, 0, ND);
            float4 b = reinterpret_cast<const float4*>(amb1)[cg];
            float bb[4] = {b.x, b.y, b.z, b.w};
            #pragma unroll
            for (int c = 0; c < 4; ++c)
                #pragma unroll
                for (int q = 0; q < 4; ++q) v[c*4+q] = fmaxf(v[c*4+q] + bb[c], 0.f);
            store4(a1m, j4, h, v);
        } else {
            int u = tid - 224, h = u & 1, cg = u >> 1, j4 = 4 * cg;
            gaccum44(v, xs, alw1, SHD, j4, h, 0, ND);
            float4 b = reinterpret_cast<const float4*>(alb1)[cg];
            float bb[4] = {b.x, b.y, b.z, b.w};
            #pragma unroll
            for (int c = 0; c < 4; ++c)
                #pragma unroll
                for (int q = 0; q < 4; ++q) v[c*4+q] = fmaxf(v[c*4+q] + bb[c], 0.f);
            store4(a1l, j4, h, v);
        }
        __syncthreads();

        // ======== Stage B: f2, 8col x 4row, 4 warp-uniform K-splits; ALL partials to cb ========
        {
            int s = tid >> 6, u = tid & 63, h = u & 1, cg = u >> 1, j8 = 8 * cg;
            float v32[32];
            gaccum84(v32, h1, fw2, HID, j8, h, s * 64, 64);
            store8(cb, s * 256 + j8, h, v32);
        }
        __syncthreads();

        // ======== Stage B2: h2 combine (256t, 1 col each) + finish ||k||^2 ========
        {
            float acc8[8] = {0,0,0,0,0,0,0,0};
            #pragma unroll
            for (int s = 0; s < 4; ++s) {
                float t8[8];
                load_row8(cb, s * 256 + tid, t8);
                #pragma unroll
                for (int m = 0; m < 8; ++m) acc8[m] += t8[m];
            }
            float b = fb2[tid];
            #pragma unroll
            for (int m = 0; m < 8; ++m) acc8[m] = fast_softplus(acc8[m] + b);
            store_row8(h2, tid, acc8);
            if (tid < 8) kn2s[tid] = redk[tid] + redk[8 + tid];
        }
        __syncthreads();

        // ======== Stage C1: f3, 4x4, 4 warp-uniform K-splits; ALL partials to cb ========
        {
            int s = tid >> 6, u = tid & 63, h = u & 1, cg = u >> 1, j4 = 4 * cg;
            gaccum44(v, h2, fw3, ND, j4, h, s * 64, 64);
            store4(cb, s * 128 + j4, h, v);
        }
        __syncthreads();

        // ======== Stage C2: f3 combine (128t) || am2 (32t, 4x4) || al2 (32t, 4x4) ========
        if (tid < 128) {
            float r8[8] = {0,0,0,0,0,0,0,0};
            #pragma unroll
            for (int s = 0; s < 4; ++s) {
                float4 c0 = ldchunk_f(cb, (s * 128 + tid) * 2);
                float4 c1 = ldchunk_f(cb, (s * 128 + tid) * 2 + 1);
                r8[0]+=c0.x; r8[1]+=c0.y; r8[2]+=c0.z; r8[3]+=c0.w;
                r8[4]+=c1.x; r8[5]+=c1.y; r8[6]+=c1.z; r8[7]+=c1.w;
            }
            float b = fb3[tid];
            #pragma unroll
            for (int m = 0; m < 8; ++m) r8[m] += b;
            store_row8(fo, tid, r8);
        } else if (tid < 160) {
            int u = tid - 128, h = u & 1, cg = u >> 1, j4 = 4 * cg;
            gaccum44(v, a1m, amw2, SHD, j4, h, 0, SHD);
            float4 b = reinterpret_cast<const float4*>(amb2)[cg];
            float bb[4] = {b.x, b.y, b.z, b.w};
            #pragma unroll
            for (int c = 0; c < 4; ++c)
                #pragma unroll
                for (int q = 0; q < 4; ++q) v[c*4+q] = fmaxf(v[c*4+q] + bb[c], 0.f);
            store4(a2m, j4, h, v);
        } else if (tid < 192) {
            int u = tid - 160, h = u & 1, cg = u >> 1, j4 = 4 * cg;
            gaccum44(v, a1l, alw2, SHD, j4, h, 0, SHD);
            float4 b = reinterpret_cast<const float4*>(alb2)[cg];
            float bb[4] = {b.x, b.y, b.z, b.w};
            #pragma unroll
            for (int c = 0; c < 4; ++c)
                #pragma unroll
                for (int q = 0; q < 4; ++q) v[c*4+q] = fmaxf(v[c*4+q] + bb[c], 0.f);
            store4(a2l, j4, h, v);
        }
        __syncthreads();

        // ======== Stage C3: am3 (128t, 4x4, Ksplit2) || al3 (128t, 4x4, Ksplit2); partials to cb ========
        // Bias + tanh/linear applied in stage E after combine.
        if (tid < 128) {
            int s = tid >> 6, u = tid & 63, h = u & 1, cg = u >> 1, j4 = 4 * cg;
            gaccum44(v, a2m, amw3, ND, j4, h, s * 32, 32);
            store4(cb, s * 128 + j4, h, v);              // am3: rows 0-255
        } else {
            int t = tid - 128, s = t >> 6, u = t & 63, h = u & 1, cg = u >> 1, j4 = 4 * cg;
            gaccum44(v, a2l, alw3, ND, j4, h, s * 32, 32);
            store4(cb, 256 + s * 128 + j4, h, v);        // al3: rows 256-511
        }
        __syncthreads();

        // ======== Stage E: combine am3/al3, g, f+g, u_f, u_g ========
        {
            float4 kv = ldchunk_f(ko,  ewj * 2 + ewc);
            float4 fv = ldchunk_f(fo,  ewj * 2 + ewc);
            float4 m0 = ldchunk_f(cb, ewj * 2 + ewc);
            float4 m1 = ldchunk_f(cb, (128 + ewj) * 2 + ewc);
            float4 l0 = ldchunk_f(cb, (256 + ewj) * 2 + ewc);
            float4 l1 = ldchunk_f(cb, (384 + ewj) * 2 + ewc);
            float bam = amb3[ewj], bal = alb3[ewj];
            float kk[4] = {kv.x, kv.y, kv.z, kv.w};
            float ff[4] = {fv.x, fv.y, fv.z, fv.w};
            float mm[4] = {m0.x + m1.x + bam, m0.y + m1.y + bam,
                           m0.z + m1.z + bam, m0.w + m1.w + bam};
            float ll[4] = {l0.x + l1.x + bal, l0.y + l1.y + bal,
                           l0.z + l1.z + bal, l0.w + l1.w + bal};
            float gs[4], uf[4], ug[4];
            #pragma unroll
            for (int q = 0; q < 4; ++q) {
                float m = fast_tanh(mm[q]);
                float sd = fast_softplus(san(ll[q]));
                float g = fast_tanh(san(m) + sd * nse[q]);
                float om = 1.f - kk[q] * kk[q];
                gs[q] = ff[q] + g;
                uf[q] = om * ff[q];
                ug[q] = om * g;
            }
            stchunk_f(go,  ewj * 2 + ewc, make_float4(gs[0], gs[1], gs[2], gs[3]));
            stchunk_f(ubf, ewj * 2 + ewc, make_float4(uf[0], uf[1], uf[2], uf[3]));
            stchunk_f(ubg, ewj * 2 + ewc, make_float4(ug[0], ug[1], ug[2], ug[3]));
        }
        __syncthreads();

        // ======== Stage F: jacf (128t) || jacg (128t), 4x4, 2 warp-uniform K-splits ========
        if (tid < 128) {
            int s = tid >> 6, u = tid & 63, h = u & 1, cg = u >> 1, j4 = 4 * cg;
            gaccum44(v, ubf, kw, ND, j4, h, s * 64, 64);
            store4(cb, s * 128 + j4, h, v);              // rows 0-255
        } else {
            int t = tid - 128, s = t >> 6, u = t & 63, h = u & 1, cg = u >> 1, j4 = 4 * cg;
            gaccum44(v, ubg, kw, ND, j4, h, s * 64, 64);
            store4(cb, 256 + s * 128 + j4, h, v);        // rows 256-511
        }
        __syncthreads();

        // ======== Stage F2: combine + reduce ========
        if (tid < 128) {
            float va[8], wa[8];
            load_row8(cb, tid, va); load_row8(cb, 128 + tid, wa);
            float sq[8];
            #pragma unroll
            for (int m = 0; m < 8; ++m) { float x = va[m] + wa[m]; sq[m] = x * x; }
            warp_reduce8(sq);
            if ((tid & 31) == 0) {
                int w = tid >> 5;
                #pragma unroll
                for (int m = 0; m < 8; ++m) redf[w * 8 + m] = sq[m];
            }
        } else {
            int col = tid - 128;
            float va[8], wa[8], kr[8];
            load_row8(cb, 256 + col, va); load_row8(cb, 384 + col, wa);
            load_row8(ko, col, kr);
            float sq[8];
            #pragma unroll
            for (int m = 0; m < 8; ++m) sq[m] = (va[m] + wa[m]) * kr[m];
            warp_reduce8(sq);
            if ((tid & 31) == 0) {
                int w = (tid - 128) >> 5;
                #pragma unroll
                for (int m = 0; m < 8; ++m) redg[w * 8 + m] = sq[m];
            }
        }
        __syncthreads();

        // ======== Update: inline mask + Euler + output ========
        {
            float sclq[4];
            #pragma unroll
            for (int q = 0; q < 4; ++q) {
                int m = 4 * ewc + q;
                float kn2 = kn2s[m];
                float jf2 = redf[m] + redf[8 + m] + redf[16 + m] + redf[24 + m];
                float c2v = redg[m] + redg[8 + m] + redg[16 + m] + redg[24 + m];
                float kn = sqrtf(kn2);
                float kn9 = kn2 * kn2 * kn2 * kn2 * kn;
                float c1 = sqrtf(jf2) - 60.0f * kn9;
                float c2 = c2v - 20.0f * kn9 * kn;
                bool mask = (c1 > 1e-8f) || (c2 < -1e-8f);
                sclq[q] = mask ? (0.5f * dt) : dt;
            }
            float4 xv = ldchunk_f(xs, ewj * 2 + ewc);
            float4 dv = ldchunk_f(go, ewj * 2 + ewc);
            float x[4] = {xv.x, xv.y, xv.z, xv.w};
            float d[4] = {dv.x, dv.y, dv.z, dv.w};
            float o[4];
            float* ob = out + (size_t)(step + 1) * BSZ * ND;
            #pragma unroll
            for (int q = 0; q < 4; ++q) {
                int m = 4 * ewc + q;
                o[q] = x[q] + d[q] * sclq[q];
                ob[(size_t)(r0 + m) * ND + ewj] = o[q];
            }
            stchunk_f(xs, ewj * 2 + ewc, make_float4(o[0], o[1], o[2], o[3]));
        }
        __syncthreads();
    }
}

extern "C" void kernel_launch(void* const* d_in, const int* in_sizes, int n_in,
                              void* d_out, int out_size) {
    (void)in_sizes; (void)n_in; (void)out_size;
    const float* y0   = (const float*)d_in[0];
    const float* tv   = (const float*)d_in[1];
    const float* nz   = (const float*)d_in[2];
    const float* fw1  = (const float*)d_in[3];
    const float* fb1  = (const float*)d_in[4];
    const float* fw2  = (const float*)d_in[5];
    const float* fb2  = (const float*)d_in[6];
    const float* fw3  = (const float*)d_in[7];
    const float* fb3  = (const float*)d_in[8];
    const float* amw1 = (const float*)d_in[9];
    const float* amb1 = (const float*)d_in[10];
    const float* amw2 = (const float*)d_in[11];
    const float* amb2 = (const float*)d_in[12];
    const float* amw3 = (const float*)d_in[13];
    const float* amb3 = (const float*)d_in[14];
    const float* alw1 = (const float*)d_in[15];
    const float* alb1 = (const float*)d_in[16];
    const float* alw2 = (const float*)d_in[17];
    const float* alb2 = (const float*)d_in[18];
    const float* alw3 = (const float*)d_in[19];
    const float* alb3 = (const float*)d_in[20];
    const float* kw   = (const float*)d_in[21];
    float* out = (float*)d_out;

    const int shmem = 20568 * sizeof(float);  // ~82.3 KB -> 2 blocks/SM
    cudaFuncSetAttribute(node_kernel, cudaFuncAttributeMaxDynamicSharedMemorySize, shmem);
    node_kernel<<<NBLOCKS, NTHR, shmem>>>(
        y0, tv, nz, fw1, fb1, fw2, fb2, fw3, fb3,
        amw1, amb1, amw2, amb2, amw3, amb3,
        alw1, alb1, alw2, alb2, alw3, alb3, kw, out);
}